// round 16
// baseline (speedup 1.0000x reference)
#include <cuda_runtime.h>
#include <cuda_fp16.h>
#include <math.h>

#define L 64
static const int NMAX = 100352;
static const int EMAX = 1605632;

__device__ __align__(16) float g_deg[NMAX];
__device__ __align__(16) float g_dinv[NMAX];
__device__ __align__(16) float g_rcp[NMAX];
__device__ __align__(16) float g_a[NMAX];
__device__ __align__(16) float g_c[NMAX];
__device__ int   g_cnti[NMAX];
__device__ int   g_offs[NMAX];
__device__ int   g_cursor[NMAX];
__device__ int   g_bsums[1024];
__device__ __align__(16) uint2 g_csr[EMAX];   // .x = row idx, .y = norm bits
__device__ __align__(16) int   g_eid[EMAX];
__device__ __align__(16) float g_u[64];
__device__ __align__(16) float g_v[64];
__device__ __align__(16) __half2 g_hh0[(size_t)NMAX * 32];
__device__ __align__(16) __half2 g_hh1[(size_t)NMAX * 32];
__device__ __align__(16) __half2 g_hhT[(size_t)NMAX * 32];  // agg scratch (fp16)
__device__ __align__(16) float g_t1[(size_t)NMAX * L];      // decoder B (fp32)
__device__ int   g_is64;

__device__ __forceinline__ int ld_idx(const void* p, int e, int is64) {
    if (is64) return (int)((const long long*)p)[e];
    return ((const int*)p)[e];
}

// zero deg/cnt + index-dtype detection fused
__global__ void k_zero2(float* pf, int* pi, int n, const unsigned int* er) {
    int i = blockIdx.x * blockDim.x + threadIdx.x;
    if (i < n) { pf[i] = 0.0f; pi[i] = 0; }
    if (blockIdx.x == 0 && threadIdx.x == 0) {
        int ok = 1;
        #pragma unroll
        for (int j = 0; j < 64; j++)
            if (er[2 * j + 1] != 0u) ok = 0;
        g_is64 = ok;
    }
}

__global__ void k_deg_cnt(const float* __restrict__ attr, const void* colp, int E) {
    int is64 = g_is64;
    int e = blockIdx.x * blockDim.x + threadIdx.x;
    if (e < E) {
        int c = ld_idx(colp, e, is64);
        atomicAdd(&g_deg[c], attr[e]);
        atomicAdd(&g_cnti[c], 1);
    }
}

// ---------------- prefix scan over counts -----------------------------------
__global__ void k_scan1(int N) {
    __shared__ int wsum[8];
    int t = threadIdx.x;
    int base = blockIdx.x * 1024 + t * 4;
    int v0 = 0, v1 = 0, v2 = 0, v3 = 0;
    if (base + 0 < N) v0 = g_cnti[base + 0];
    if (base + 1 < N) v1 = g_cnti[base + 1];
    if (base + 2 < N) v2 = g_cnti[base + 2];
    if (base + 3 < N) v3 = g_cnti[base + 3];
    int s = v0 + v1 + v2 + v3;
    int lane = t & 31, warp = t >> 5;
    int x = s;
    #pragma unroll
    for (int o = 1; o < 32; o <<= 1) {
        int y = __shfl_up_sync(0xffffffffu, x, o);
        if (lane >= o) x += y;
    }
    if (lane == 31) wsum[warp] = x;
    __syncthreads();
    if (warp == 0 && lane < 8) {
        int w = wsum[lane];
        #pragma unroll
        for (int o = 1; o < 8; o <<= 1) {
            int y = __shfl_up_sync(0x000000ffu, w, o);
            if (lane >= o) w += y;
        }
        wsum[lane] = w;
    }
    __syncthreads();
    int excl = x - s + (warp > 0 ? wsum[warp - 1] : 0);
    int r = excl;
    r += v0; if (base + 0 < N) g_offs[base + 0] = r;
    r += v1; if (base + 1 < N) g_offs[base + 1] = r;
    r += v2; if (base + 2 < N) g_offs[base + 2] = r;
    r += v3; if (base + 3 < N) g_offs[base + 3] = r;
    if (t == 255) g_bsums[blockIdx.x] = excl + s;
}

// parallel exclusive scan of nb block sums (nb <= 128), one block of 128
__global__ void k_scan2(int nb) {
    __shared__ int ws[4];
    int t = threadIdx.x;
    int lane = t & 31, warp = t >> 5;
    int v = (t < nb) ? g_bsums[t] : 0;
    int x = v;
    #pragma unroll
    for (int o = 1; o < 32; o <<= 1) {
        int y = __shfl_up_sync(0xffffffffu, x, o);
        if (lane >= o) x += y;
    }
    if (lane == 31) ws[warp] = x;
    __syncthreads();
    if (warp == 0 && lane < 4) {
        int w = ws[lane];
        #pragma unroll
        for (int o = 1; o < 4; o <<= 1) {
            int y = __shfl_up_sync(0x0000000fu, w, o);
            if (lane >= o) w += y;
        }
        ws[lane] = w;
    }
    __syncthreads();
    int excl = x - v + (warp > 0 ? ws[warp - 1] : 0);
    if (t < nb) g_bsums[t] = excl;
}

__global__ void k_scan3(int N) {
    int i = blockIdx.x * blockDim.x + threadIdx.x;
    if (i < N) {
        int cnt = g_cnti[i];
        int excl = g_offs[i] + g_bsums[i >> 10] - cnt;
        g_offs[i] = excl;
        g_cursor[i] = excl;
        float d = g_deg[i];
        g_dinv[i] = (d > 0.0f) ? rsqrtf(fmaxf(d, 1e-30f)) : 0.0f;
        g_rcp[i]  = 1.0f / fmaxf((float)cnt, 1.0f);
    }
}

__global__ void k_csr_fill(const float* __restrict__ attr, const void* rowp,
                           const void* colp, int E) {
    int is64 = g_is64;
    int e = blockIdx.x * blockDim.x + threadIdx.x;
    if (e < E) {
        int r = ld_idx(rowp, e, is64);
        int c = ld_idx(colp, e, is64);
        int p = atomicAdd(&g_cursor[c], 1);
        uint2 rec;
        rec.x = (unsigned int)r;
        rec.y = __float_as_uint(g_dinv[r] * attr[e] * g_dinv[c]);
        g_csr[p] = rec;
        g_eid[p] = e;
    }
}

__global__ void k_uv(const float* __restrict__ w_enc, const float* __restrict__ b_enc,
                     const float* __restrict__ W) {
    int g = threadIdx.x;
    float u = 0.f, v = 0.f;
    #pragma unroll
    for (int f = 0; f < 64; f++) {
        float wf = W[f * 64 + g];
        u += w_enc[f] * wf;
        v += b_enc[f] * wf;
    }
    g_u[g] = u;
    g_v[g] = v;
}

__global__ void __launch_bounds__(256)
k_l1sums(const float* __restrict__ x, int N) {
    int warp = threadIdx.x >> 5, lane = threadIdx.x & 31;
    int n = blockIdx.x * 8 + warp;
    if (n >= N) return;
    int st = g_offs[n];
    int en = st + g_cnti[n];
    float s1 = 0.f, s0 = 0.f;
    for (int k = st + lane; k < en; k += 32) {
        uint2 rec = g_csr[k];
        float nm = __uint_as_float(rec.y);
        s1 += nm * x[rec.x];
        s0 += nm;
    }
    #pragma unroll
    for (int off = 16; off; off >>= 1) {
        s1 += __shfl_down_sync(0xffffffffu, s1, off);
        s0 += __shfl_down_sync(0xffffffffu, s0, off);
    }
    if (lane == 0) {
        float rcp = g_rcp[n];
        g_a[n] = s1 * rcp;
        g_c[n] = s0 * rcp;
    }
}

__global__ void k_l1out(const float* __restrict__ b1, __half2* __restrict__ hout, int N) {
    int i = blockIdx.x * blockDim.x + threadIdx.x;   // over N*32 half2
    if (i < N * 32) {
        int n = i >> 5, f2 = (i & 31) * 2;
        float an = g_a[n], cn = g_c[n];
        float v0 = fmaxf(an * g_u[f2]     + cn * g_v[f2]     + b1[f2],     0.f);
        float v1 = fmaxf(an * g_u[f2 + 1] + cn * g_v[f2 + 1] + b1[f2 + 1], 0.f);
        hout[i] = __floats2half2_rn(v0, v1);
    }
}

// ---- aggregation over fp16 h -> fp16 out, csr-prefetch pipelined ------------
__global__ void __launch_bounds__(256)
k_agg(const __half2* __restrict__ hin, __half2* __restrict__ aggo, int N) {
    int warp = threadIdx.x >> 5, lane = threadIdx.x & 31;
    int n = blockIdx.x * 8 + warp;
    if (n >= N) return;
    int g  = lane >> 3;
    int sl = lane & 7;
    int st = g_offs[n];
    int en = st + g_cnti[n];
    float2 a0 = make_float2(0.f, 0.f), a1 = a0, a2 = a0, a3 = a0;
    // prefetch first record (cnt >= 1 always: self-loops)
    int e0i = st + g;
    uint2 rec = g_csr[e0i < en - 1 ? e0i : en - 1];
    #pragma unroll 1
    for (int k = st; k < en; k += 4) {
        int e = k + g;
        uint2 cr = rec;
        int enx = k + 4 + g;
        if (k + 4 < en)
            rec = g_csr[enx < en - 1 ? enx : en - 1];   // prefetch next iter
        float nm = (e < en) ? __uint_as_float(cr.y) : 0.f;
        const uint4 v = ((const uint4*)(hin + ((size_t)cr.x << 5)))[sl];
        float2 f0 = __half22float2(*(const __half2*)&v.x);
        float2 f1 = __half22float2(*(const __half2*)&v.y);
        float2 f2 = __half22float2(*(const __half2*)&v.z);
        float2 f3 = __half22float2(*(const __half2*)&v.w);
        a0.x += f0.x * nm; a0.y += f0.y * nm;
        a1.x += f1.x * nm; a1.y += f1.y * nm;
        a2.x += f2.x * nm; a2.y += f2.y * nm;
        a3.x += f3.x * nm; a3.y += f3.y * nm;
    }
    #pragma unroll
    for (int off = 8; off <= 16; off <<= 1) {
        a0.x += __shfl_xor_sync(0xffffffffu, a0.x, off);
        a0.y += __shfl_xor_sync(0xffffffffu, a0.y, off);
        a1.x += __shfl_xor_sync(0xffffffffu, a1.x, off);
        a1.y += __shfl_xor_sync(0xffffffffu, a1.y, off);
        a2.x += __shfl_xor_sync(0xffffffffu, a2.x, off);
        a2.y += __shfl_xor_sync(0xffffffffu, a2.y, off);
        a3.x += __shfl_xor_sync(0xffffffffu, a3.x, off);
        a3.y += __shfl_xor_sync(0xffffffffu, a3.y, off);
    }
    if (lane < 8) {
        float rcp = g_rcp[n];
        __half2 h0 = __floats2half2_rn(a0.x * rcp, a0.y * rcp);
        __half2 h1 = __floats2half2_rn(a1.x * rcp, a1.y * rcp);
        __half2 h2 = __floats2half2_rn(a2.x * rcp, a2.y * rcp);
        __half2 h3 = __floats2half2_rn(a3.x * rcp, a3.y * rcp);
        uint4 o = make_uint4(*(unsigned*)&h0, *(unsigned*)&h1,
                             *(unsigned*)&h2, *(unsigned*)&h3);
        *(uint4*)(aggo + ((size_t)n << 5) + sl * 4) = o;
    }
}

// ---- tensor-core GEMM helpers -----------------------------------------------
__device__ __forceinline__ void mma16816(float* c, unsigned a0, unsigned a1,
                                         unsigned a2, unsigned a3,
                                         unsigned b0, unsigned b1) {
    asm volatile(
        "mma.sync.aligned.m16n8k16.row.col.f32.f16.f16.f32 "
        "{%0,%1,%2,%3}, {%4,%5,%6,%7}, {%8,%9}, {%0,%1,%2,%3};"
        : "+f"(c[0]), "+f"(c[1]), "+f"(c[2]), "+f"(c[3])
        : "r"(a0), "r"(a1), "r"(a2), "r"(a3), "r"(b0), "r"(b1));
}

// ---- MMA GEMM: fp16 X -> fp16 out (+bias, relu), layer GEMM -----------------
__global__ void __launch_bounds__(256)
k_gemm_mma_h2h(const __half2* __restrict__ X, const float* __restrict__ W,
               const float* __restrict__ bias, __half2* __restrict__ Y, int ntiles) {
    __shared__ __half Xs[64][72];
    __shared__ __half Wt[64][72];   // transposed W: Wt[n][k]
    int tid = threadIdx.x;
    int warp = tid >> 5, lane = tid & 31;
    int g = lane >> 2, t = lane & 3;
    int wm = (warp >> 1) * 16;
    int wn = (warp & 1) * 32;
    for (int idx = tid; idx < 4096; idx += 256) {
        int k = idx >> 6, n = idx & 63;
        Wt[n][k] = __float2half(W[idx]);
    }
    float2 bb[4];
    #pragma unroll
    for (int nt = 0; nt < 4; nt++)
        bb[nt] = *(const float2*)(bias + wn + nt * 8 + 2 * t);

    for (int tt = blockIdx.x; tt < ntiles; tt += gridDim.x) {
        __syncthreads();
        size_t hbase = (size_t)tt * 2048;
        const uint4* X4 = (const uint4*)(X + hbase);
        #pragma unroll
        for (int i = 0; i < 2; i++) {
            int idx = tid + i * 256;
            uint4 v = X4[idx];
            int row = idx >> 3;
            int c0  = (idx & 7) * 8;
            *(uint4*)&Xs[row][c0] = v;
        }
        __syncthreads();
        float c[4][4];
        #pragma unroll
        for (int nt = 0; nt < 4; nt++)
            c[nt][0] = c[nt][1] = c[nt][2] = c[nt][3] = 0.f;
        #pragma unroll
        for (int kk = 0; kk < 64; kk += 16) {
            unsigned a0 = *(const unsigned*)&Xs[wm + g][kk + 2 * t];
            unsigned a1 = *(const unsigned*)&Xs[wm + g + 8][kk + 2 * t];
            unsigned a2 = *(const unsigned*)&Xs[wm + g][kk + 2 * t + 8];
            unsigned a3 = *(const unsigned*)&Xs[wm + g + 8][kk + 2 * t + 8];
            #pragma unroll
            for (int nt = 0; nt < 4; nt++) {
                int n = wn + nt * 8 + g;
                unsigned b0 = *(const unsigned*)&Wt[n][kk + 2 * t];
                unsigned b1 = *(const unsigned*)&Wt[n][kk + 2 * t + 8];
                mma16816(c[nt], a0, a1, a2, a3, b0, b1);
            }
        }
        size_t ybase = (size_t)tt * 2048;
        int colh = (wn >> 1) + t;
        #pragma unroll
        for (int nt = 0; nt < 4; nt++) {
            float o0 = fmaxf(c[nt][0] + bb[nt].x, 0.f);
            float o1 = fmaxf(c[nt][1] + bb[nt].y, 0.f);
            float o2 = fmaxf(c[nt][2] + bb[nt].x, 0.f);
            float o3 = fmaxf(c[nt][3] + bb[nt].y, 0.f);
            Y[ybase + (size_t)(wm + g) * 32 + colh + nt * 4]     = __floats2half2_rn(o0, o1);
            Y[ybase + (size_t)(wm + g + 8) * 32 + colh + nt * 4] = __floats2half2_rn(o2, o3);
        }
    }
}

// ---- fused decoder GEMM: fp16 X -> A (fp16, W rows 0..63), B (fp32, 64..127) -
__global__ void __launch_bounds__(256)
k_gemm_mma_dec(const __half2* __restrict__ X, const float* __restrict__ W,
               __half2* __restrict__ YA, float* __restrict__ YB, int ntiles) {
    __shared__ __half Xs[64][72];
    __shared__ __half WtA[64][72];
    __shared__ __half WtB[64][72];
    int tid = threadIdx.x;
    int warp = tid >> 5, lane = tid & 31;
    int g = lane >> 2, t = lane & 3;
    int wm = (warp >> 1) * 16;
    int wn = (warp & 1) * 32;
    for (int idx = tid; idx < 4096; idx += 256) {
        int k = idx >> 6, n = idx & 63;
        WtA[n][k] = __float2half(W[idx]);
        WtB[n][k] = __float2half(W[idx + 4096]);
    }

    for (int tt = blockIdx.x; tt < ntiles; tt += gridDim.x) {
        __syncthreads();
        size_t hbase = (size_t)tt * 2048;
        const uint4* X4 = (const uint4*)(X + hbase);
        #pragma unroll
        for (int i = 0; i < 2; i++) {
            int idx = tid + i * 256;
            uint4 v = X4[idx];
            int row = idx >> 3;
            int c0  = (idx & 7) * 8;
            *(uint4*)&Xs[row][c0] = v;
        }
        __syncthreads();
        float cA[4][4], cB[4][4];
        #pragma unroll
        for (int nt = 0; nt < 4; nt++) {
            cA[nt][0] = cA[nt][1] = cA[nt][2] = cA[nt][3] = 0.f;
            cB[nt][0] = cB[nt][1] = cB[nt][2] = cB[nt][3] = 0.f;
        }
        #pragma unroll
        for (int kk = 0; kk < 64; kk += 16) {
            unsigned a0 = *(const unsigned*)&Xs[wm + g][kk + 2 * t];
            unsigned a1 = *(const unsigned*)&Xs[wm + g + 8][kk + 2 * t];
            unsigned a2 = *(const unsigned*)&Xs[wm + g][kk + 2 * t + 8];
            unsigned a3 = *(const unsigned*)&Xs[wm + g + 8][kk + 2 * t + 8];
            #pragma unroll
            for (int nt = 0; nt < 4; nt++) {
                int n = wn + nt * 8 + g;
                unsigned b0 = *(const unsigned*)&WtA[n][kk + 2 * t];
                unsigned b1 = *(const unsigned*)&WtA[n][kk + 2 * t + 8];
                mma16816(cA[nt], a0, a1, a2, a3, b0, b1);
                unsigned d0 = *(const unsigned*)&WtB[n][kk + 2 * t];
                unsigned d1 = *(const unsigned*)&WtB[n][kk + 2 * t + 8];
                mma16816(cB[nt], a0, a1, a2, a3, d0, d1);
            }
        }
        size_t yab = (size_t)tt * 2048;
        int colh = (wn >> 1) + t;
        #pragma unroll
        for (int nt = 0; nt < 4; nt++) {
            YA[yab + (size_t)(wm + g) * 32 + colh + nt * 4]     = __floats2half2_rn(cA[nt][0], cA[nt][1]);
            YA[yab + (size_t)(wm + g + 8) * 32 + colh + nt * 4] = __floats2half2_rn(cA[nt][2], cA[nt][3]);
        }
        size_t base = (size_t)tt * 4096;
        #pragma unroll
        for (int nt = 0; nt < 4; nt++) {
            int col = wn + nt * 8 + 2 * t;
            *(float2*)(YB + base + (size_t)(wm + g) * 64 + col)     = make_float2(cB[nt][0], cB[nt][1]);
            *(float2*)(YB + base + (size_t)(wm + g + 8) * 64 + col) = make_float2(cB[nt][2], cB[nt][3]);
        }
    }
}

// ---- decoder, CSR order, fp16 A gather --------------------------------------
__global__ void __launch_bounds__(256)
k_dec_csr(const __half2* __restrict__ A, const float* __restrict__ B,
          const float* __restrict__ b1, const float* __restrict__ w2,
          const float* __restrict__ b2, float* __restrict__ out, int N) {
    int warp = threadIdx.x >> 5, lane = threadIdx.x & 31;
    int n = blockIdx.x * 8 + warp;
    if (n >= N) return;
    int lane2 = lane * 2;
    float2 bias = *(const float2*)(b1 + lane2);
    float2 w    = *(const float2*)(w2 + lane2);
    float  bout = b2[0];
    float2 bc   = *(const float2*)(B + ((size_t)n << 6) + lane2);
    bc.x += bias.x; bc.y += bias.y;
    int st = g_offs[n];
    int en = st + g_cnti[n];
    int k = st;
    #pragma unroll 1
    for (; k + 2 <= en; k += 2) {
        uint2 rec0 = g_csr[k];
        uint2 rec1 = g_csr[k + 1];
        int r0 = (int)rec0.x, r1 = (int)rec1.x;
        float2 a0 = __half22float2(A[((size_t)r0 << 5) + lane]);
        float2 a1 = __half22float2(A[((size_t)r1 << 5) + lane]);
        float s0 = fmaxf(a0.x + bc.x, 0.f) * w.x + fmaxf(a0.y + bc.y, 0.f) * w.y;
        float s1 = fmaxf(a1.x + bc.x, 0.f) * w.x + fmaxf(a1.y + bc.y, 0.f) * w.y;
        #pragma unroll
        for (int off = 16; off; off >>= 1) {
            s0 += __shfl_down_sync(0xffffffffu, s0, off);
            s1 += __shfl_down_sync(0xffffffffu, s1, off);
        }
        if (lane == 0) {
            float v0 = s0 + bout;
            float v1 = s1 + bout;
            if (r0 == n) v0 = fmaxf(v0, 0.f) + log1pf(expf(-fabsf(v0)));
            if (r1 == n) v1 = fmaxf(v1, 0.f) + log1pf(expf(-fabsf(v1)));
            out[g_eid[k]]     = v0;
            out[g_eid[k + 1]] = v1;
        }
    }
    if (k < en) {
        uint2 rec = g_csr[k];
        int r = (int)rec.x;
        float2 a = __half22float2(A[((size_t)r << 5) + lane]);
        float s = fmaxf(a.x + bc.x, 0.f) * w.x + fmaxf(a.y + bc.y, 0.f) * w.y;
        #pragma unroll
        for (int off = 16; off; off >>= 1)
            s += __shfl_down_sync(0xffffffffu, s, off);
        if (lane == 0) {
            float val = s + bout;
            if (r == n) val = fmaxf(val, 0.f) + log1pf(expf(-fabsf(val)));
            out[g_eid[k]] = val;
        }
    }
}

extern "C" void kernel_launch(void* const* d_in, const int* in_sizes, int n_in,
                              void* d_out, int out_size) {
    const float* x        = (const float*)d_in[0];
    const float* eattr    = (const float*)d_in[1];
    const float* w_enc    = (const float*)d_in[2];
    const float* b_enc    = (const float*)d_in[3];
    const float* conv1_w  = (const float*)d_in[4];
    const float* conv1_b  = (const float*)d_in[5];
    const float* conv2_w  = (const float*)d_in[6];
    const float* conv2_b  = (const float*)d_in[7];
    const float* dec_w1   = (const float*)d_in[8];
    const float* dec_b1   = (const float*)d_in[9];
    const float* dec_w2   = (const float*)d_in[10];
    const float* dec_b2   = (const float*)d_in[11];
    const void*  rowp     = d_in[12];
    const void*  colp     = d_in[13];
    float* out = (float*)d_out;

    const int N = in_sizes[0];
    const int E = in_sizes[1];

    float *p_deg, *p_t1;
    int *p_cnti;
    __half2 *p_hh0, *p_hh1, *p_hhT;
    cudaGetSymbolAddress((void**)&p_deg, g_deg);
    cudaGetSymbolAddress((void**)&p_t1,  g_t1);
    cudaGetSymbolAddress((void**)&p_cnti, g_cnti);
    cudaGetSymbolAddress((void**)&p_hh0, g_hh0);
    cudaGetSymbolAddress((void**)&p_hh1, g_hh1);
    cudaGetSymbolAddress((void**)&p_hhT, g_hhT);

    const int TB = 256;
    int eb  = (E + TB - 1) / TB;
    int nb  = (N + TB - 1) / TB;
    int nhb = (N * 32 + TB - 1) / TB;
    int ntiles = (N + 63) / 64;
    int gg  = (ntiles + 1) / 2;
    int ab  = (N + 7) / 8;
    int nsb = (N + 1023) / 1024;

    k_zero2<<<nb, TB>>>(p_deg, p_cnti, N, (const unsigned int*)rowp);
    k_deg_cnt<<<eb, TB>>>(eattr, colp, E);

    k_scan1<<<nsb, 256>>>(N);
    k_scan2<<<1, 128>>>(nsb);
    k_scan3<<<nb, TB>>>(N);
    k_csr_fill<<<eb, TB>>>(eattr, rowp, colp, E);

    // layer 1 (collapsed rank-2 form) -> hh0 (fp16)
    k_uv<<<1, 64>>>(w_enc, b_enc, conv1_w);
    k_l1sums<<<ab, TB>>>(x, N);
    k_l1out<<<nhb, TB>>>(conv1_b, p_hh0, N);

    // layers 2..6: agg(fp16 -> fp16 hhT), MMA gemm h2h (hhT -> nxt)
    const float* Ws[5] = { conv2_w,            conv1_w + 4096, conv2_w + 4096,
                           conv1_w + 2*4096,   conv2_w + 2*4096 };
    const float* Bs[5] = { conv2_b,            conv1_b + 64,   conv2_b + 64,
                           conv1_b + 2*64,     conv2_b + 2*64 };
    __half2* cur = p_hh0;
    __half2* nxt = p_hh1;
    for (int i = 0; i < 5; i++) {
        k_agg<<<ab, TB>>>(cur, p_hhT, N);
        k_gemm_mma_h2h<<<gg, TB>>>(p_hhT, Ws[i], Bs[i], nxt, ntiles);
        { __half2* t = cur; cur = nxt; nxt = t; }
    }
    // after 5 layers: cur = hh1, nxt = hh0 (free)

    // fused decoder GEMM: A (fp16) -> nxt, B (fp32) -> t1
    k_gemm_mma_dec<<<gg, TB>>>(cur, dec_w1, nxt, p_t1, ntiles);
    k_dec_csr<<<ab, TB>>>(nxt, p_t1, dec_b1, dec_w2, dec_b2, out, N);
}

// round 17
// speedup vs baseline: 1.4046x; 1.4046x over previous
#include <cuda_runtime.h>
#include <cuda_fp16.h>
#include <math.h>

#define L 64
static const int NMAX = 100352;
static const int EMAX = 1605632;

__device__ __align__(16) float g_deg[NMAX];
__device__ __align__(16) float g_dinv[NMAX];
__device__ __align__(16) float g_rcp[NMAX];
__device__ __align__(16) float g_a[NMAX];
__device__ __align__(16) float g_c[NMAX];
__device__ int   g_cnti[NMAX];
__device__ int   g_offs[NMAX];
__device__ int   g_cursor[NMAX];
__device__ int   g_bsums[1024];
__device__ __align__(16) uint2 g_csr[EMAX];   // .x = row idx, .y = norm bits
__device__ __align__(16) int   g_eid[EMAX];
__device__ __align__(16) float g_u[64];
__device__ __align__(16) float g_v[64];
__device__ __align__(16) __half2 g_hh0[(size_t)NMAX * 32];
__device__ __align__(16) __half2 g_hh1[(size_t)NMAX * 32];
__device__ __align__(16) __half2 g_hhT[(size_t)NMAX * 32];  // agg scratch (fp16)
__device__ __align__(16) float g_t1[(size_t)NMAX * L];      // decoder B (fp32)
__device__ int   g_is64;

__device__ __forceinline__ int ld_idx(const void* p, int e, int is64) {
    if (is64) return (int)((const long long*)p)[e];
    return ((const int*)p)[e];
}

// zero deg/cnt + index-dtype detection fused
__global__ void k_zero2(float* pf, int* pi, int n, const unsigned int* er) {
    int i = blockIdx.x * blockDim.x + threadIdx.x;
    if (i < n) { pf[i] = 0.0f; pi[i] = 0; }
    if (blockIdx.x == 0 && threadIdx.x == 0) {
        int ok = 1;
        #pragma unroll
        for (int j = 0; j < 64; j++)
            if (er[2 * j + 1] != 0u) ok = 0;
        g_is64 = ok;
    }
}

__global__ void k_deg_cnt(const float* __restrict__ attr, const void* colp, int E) {
    int is64 = g_is64;
    int e = blockIdx.x * blockDim.x + threadIdx.x;
    if (e < E) {
        int c = ld_idx(colp, e, is64);
        atomicAdd(&g_deg[c], attr[e]);
        atomicAdd(&g_cnti[c], 1);
    }
}

// ---------------- prefix scan over counts -----------------------------------
__global__ void k_scan1(int N) {
    __shared__ int wsum[8];
    int t = threadIdx.x;
    int base = blockIdx.x * 1024 + t * 4;
    int v0 = 0, v1 = 0, v2 = 0, v3 = 0;
    if (base + 0 < N) v0 = g_cnti[base + 0];
    if (base + 1 < N) v1 = g_cnti[base + 1];
    if (base + 2 < N) v2 = g_cnti[base + 2];
    if (base + 3 < N) v3 = g_cnti[base + 3];
    int s = v0 + v1 + v2 + v3;
    int lane = t & 31, warp = t >> 5;
    int x = s;
    #pragma unroll
    for (int o = 1; o < 32; o <<= 1) {
        int y = __shfl_up_sync(0xffffffffu, x, o);
        if (lane >= o) x += y;
    }
    if (lane == 31) wsum[warp] = x;
    __syncthreads();
    if (warp == 0 && lane < 8) {
        int w = wsum[lane];
        #pragma unroll
        for (int o = 1; o < 8; o <<= 1) {
            int y = __shfl_up_sync(0x000000ffu, w, o);
            if (lane >= o) w += y;
        }
        wsum[lane] = w;
    }
    __syncthreads();
    int excl = x - s + (warp > 0 ? wsum[warp - 1] : 0);
    int r = excl;
    r += v0; if (base + 0 < N) g_offs[base + 0] = r;
    r += v1; if (base + 1 < N) g_offs[base + 1] = r;
    r += v2; if (base + 2 < N) g_offs[base + 2] = r;
    r += v3; if (base + 3 < N) g_offs[base + 3] = r;
    if (t == 255) g_bsums[blockIdx.x] = excl + s;
}

// parallel exclusive scan of nb block sums (nb <= 128), one block of 128
__global__ void k_scan2(int nb) {
    __shared__ int ws[4];
    int t = threadIdx.x;
    int lane = t & 31, warp = t >> 5;
    int v = (t < nb) ? g_bsums[t] : 0;
    int x = v;
    #pragma unroll
    for (int o = 1; o < 32; o <<= 1) {
        int y = __shfl_up_sync(0xffffffffu, x, o);
        if (lane >= o) x += y;
    }
    if (lane == 31) ws[warp] = x;
    __syncthreads();
    if (warp == 0 && lane < 4) {
        int w = ws[lane];
        #pragma unroll
        for (int o = 1; o < 4; o <<= 1) {
            int y = __shfl_up_sync(0x0000000fu, w, o);
            if (lane >= o) w += y;
        }
        ws[lane] = w;
    }
    __syncthreads();
    int excl = x - v + (warp > 0 ? ws[warp - 1] : 0);
    if (t < nb) g_bsums[t] = excl;
}

__global__ void k_scan3(int N) {
    int i = blockIdx.x * blockDim.x + threadIdx.x;
    if (i < N) {
        int cnt = g_cnti[i];
        int excl = g_offs[i] + g_bsums[i >> 10] - cnt;
        g_offs[i] = excl;
        g_cursor[i] = excl;
        float d = g_deg[i];
        g_dinv[i] = (d > 0.0f) ? rsqrtf(fmaxf(d, 1e-30f)) : 0.0f;
        g_rcp[i]  = 1.0f / fmaxf((float)cnt, 1.0f);
    }
}

__global__ void k_csr_fill(const float* __restrict__ attr, const void* rowp,
                           const void* colp, int E) {
    int is64 = g_is64;
    int e = blockIdx.x * blockDim.x + threadIdx.x;
    if (e < E) {
        int r = ld_idx(rowp, e, is64);
        int c = ld_idx(colp, e, is64);
        int p = atomicAdd(&g_cursor[c], 1);
        uint2 rec;
        rec.x = (unsigned int)r;
        rec.y = __float_as_uint(g_dinv[r] * attr[e] * g_dinv[c]);
        g_csr[p] = rec;
        g_eid[p] = e;
    }
}

__global__ void k_uv(const float* __restrict__ w_enc, const float* __restrict__ b_enc,
                     const float* __restrict__ W) {
    int g = threadIdx.x;
    float u = 0.f, v = 0.f;
    #pragma unroll
    for (int f = 0; f < 64; f++) {
        float wf = W[f * 64 + g];
        u += w_enc[f] * wf;
        v += b_enc[f] * wf;
    }
    g_u[g] = u;
    g_v[g] = v;
}

__global__ void __launch_bounds__(256)
k_l1sums(const float* __restrict__ x, int N) {
    int warp = threadIdx.x >> 5, lane = threadIdx.x & 31;
    int n = blockIdx.x * 8 + warp;
    if (n >= N) return;
    int st = g_offs[n];
    int en = st + g_cnti[n];
    float s1 = 0.f, s0 = 0.f;
    for (int k = st + lane; k < en; k += 32) {
        uint2 rec = g_csr[k];
        float nm = __uint_as_float(rec.y);
        s1 += nm * x[rec.x];
        s0 += nm;
    }
    #pragma unroll
    for (int off = 16; off; off >>= 1) {
        s1 += __shfl_down_sync(0xffffffffu, s1, off);
        s0 += __shfl_down_sync(0xffffffffu, s0, off);
    }
    if (lane == 0) {
        float rcp = g_rcp[n];
        g_a[n] = s1 * rcp;
        g_c[n] = s0 * rcp;
    }
}

__global__ void k_l1out(const float* __restrict__ b1, __half2* __restrict__ hout, int N) {
    int i = blockIdx.x * blockDim.x + threadIdx.x;   // over N*32 half2
    if (i < N * 32) {
        int n = i >> 5, f2 = (i & 31) * 2;
        float an = g_a[n], cn = g_c[n];
        float v0 = fmaxf(an * g_u[f2]     + cn * g_v[f2]     + b1[f2],     0.f);
        float v1 = fmaxf(an * g_u[f2 + 1] + cn * g_v[f2 + 1] + b1[f2 + 1], 0.f);
        hout[i] = __floats2half2_rn(v0, v1);
    }
}

// ---- aggregation over fp16 h -> fp16 out (R15 form — proven fastest) --------
__global__ void __launch_bounds__(256)
k_agg(const __half2* __restrict__ hin, __half2* __restrict__ aggo, int N) {
    int warp = threadIdx.x >> 5, lane = threadIdx.x & 31;
    int n = blockIdx.x * 8 + warp;
    if (n >= N) return;
    int g  = lane >> 3;
    int sl = lane & 7;
    int st = g_offs[n];
    int en = st + g_cnti[n];
    float2 a0 = make_float2(0.f, 0.f), a1 = a0, a2 = a0, a3 = a0;
    #pragma unroll 1
    for (int k = st; k < en; k += 4) {
        int e = k + g;
        int ec = e < en - 1 ? e : en - 1;
        uint2 rec = g_csr[ec];
        float nm = (e < en) ? __uint_as_float(rec.y) : 0.f;
        const uint4 v = ((const uint4*)(hin + ((size_t)rec.x << 5)))[sl];
        float2 f0 = __half22float2(*(const __half2*)&v.x);
        float2 f1 = __half22float2(*(const __half2*)&v.y);
        float2 f2 = __half22float2(*(const __half2*)&v.z);
        float2 f3 = __half22float2(*(const __half2*)&v.w);
        a0.x += f0.x * nm; a0.y += f0.y * nm;
        a1.x += f1.x * nm; a1.y += f1.y * nm;
        a2.x += f2.x * nm; a2.y += f2.y * nm;
        a3.x += f3.x * nm; a3.y += f3.y * nm;
    }
    #pragma unroll
    for (int off = 8; off <= 16; off <<= 1) {
        a0.x += __shfl_xor_sync(0xffffffffu, a0.x, off);
        a0.y += __shfl_xor_sync(0xffffffffu, a0.y, off);
        a1.x += __shfl_xor_sync(0xffffffffu, a1.x, off);
        a1.y += __shfl_xor_sync(0xffffffffu, a1.y, off);
        a2.x += __shfl_xor_sync(0xffffffffu, a2.x, off);
        a2.y += __shfl_xor_sync(0xffffffffu, a2.y, off);
        a3.x += __shfl_xor_sync(0xffffffffu, a3.x, off);
        a3.y += __shfl_xor_sync(0xffffffffu, a3.y, off);
    }
    if (lane < 8) {
        float rcp = g_rcp[n];
        __half2 h0 = __floats2half2_rn(a0.x * rcp, a0.y * rcp);
        __half2 h1 = __floats2half2_rn(a1.x * rcp, a1.y * rcp);
        __half2 h2 = __floats2half2_rn(a2.x * rcp, a2.y * rcp);
        __half2 h3 = __floats2half2_rn(a3.x * rcp, a3.y * rcp);
        uint4 o = make_uint4(*(unsigned*)&h0, *(unsigned*)&h1,
                             *(unsigned*)&h2, *(unsigned*)&h3);
        *(uint4*)(aggo + ((size_t)n << 5) + sl * 4) = o;
    }
}

// ---- tensor-core GEMM helpers -----------------------------------------------
__device__ __forceinline__ void mma16816(float* c, unsigned a0, unsigned a1,
                                         unsigned a2, unsigned a3,
                                         unsigned b0, unsigned b1) {
    asm volatile(
        "mma.sync.aligned.m16n8k16.row.col.f32.f16.f16.f32 "
        "{%0,%1,%2,%3}, {%4,%5,%6,%7}, {%8,%9}, {%0,%1,%2,%3};"
        : "+f"(c[0]), "+f"(c[1]), "+f"(c[2]), "+f"(c[3])
        : "r"(a0), "r"(a1), "r"(a2), "r"(a3), "r"(b0), "r"(b1));
}

// ---- MMA GEMM: fp16 X -> fp16 out (+bias, relu), layer GEMM -----------------
__global__ void __launch_bounds__(256)
k_gemm_mma_h2h(const __half2* __restrict__ X, const float* __restrict__ W,
               const float* __restrict__ bias, __half2* __restrict__ Y, int ntiles) {
    __shared__ __half Xs[64][72];
    __shared__ __half Wt[64][72];   // transposed W: Wt[n][k]
    int tid = threadIdx.x;
    int warp = tid >> 5, lane = tid & 31;
    int g = lane >> 2, t = lane & 3;
    int wm = (warp >> 1) * 16;
    int wn = (warp & 1) * 32;
    for (int idx = tid; idx < 4096; idx += 256) {
        int k = idx >> 6, n = idx & 63;
        Wt[n][k] = __float2half(W[idx]);
    }
    float2 bb[4];
    #pragma unroll
    for (int nt = 0; nt < 4; nt++)
        bb[nt] = *(const float2*)(bias + wn + nt * 8 + 2 * t);

    for (int tt = blockIdx.x; tt < ntiles; tt += gridDim.x) {
        __syncthreads();
        size_t hbase = (size_t)tt * 2048;
        const uint4* X4 = (const uint4*)(X + hbase);
        #pragma unroll
        for (int i = 0; i < 2; i++) {
            int idx = tid + i * 256;
            uint4 v = X4[idx];
            int row = idx >> 3;
            int c0  = (idx & 7) * 8;
            *(uint4*)&Xs[row][c0] = v;
        }
        __syncthreads();
        float c[4][4];
        #pragma unroll
        for (int nt = 0; nt < 4; nt++)
            c[nt][0] = c[nt][1] = c[nt][2] = c[nt][3] = 0.f;
        #pragma unroll
        for (int kk = 0; kk < 64; kk += 16) {
            unsigned a0 = *(const unsigned*)&Xs[wm + g][kk + 2 * t];
            unsigned a1 = *(const unsigned*)&Xs[wm + g + 8][kk + 2 * t];
            unsigned a2 = *(const unsigned*)&Xs[wm + g][kk + 2 * t + 8];
            unsigned a3 = *(const unsigned*)&Xs[wm + g + 8][kk + 2 * t + 8];
            #pragma unroll
            for (int nt = 0; nt < 4; nt++) {
                int n = wn + nt * 8 + g;
                unsigned b0 = *(const unsigned*)&Wt[n][kk + 2 * t];
                unsigned b1 = *(const unsigned*)&Wt[n][kk + 2 * t + 8];
                mma16816(c[nt], a0, a1, a2, a3, b0, b1);
            }
        }
        size_t ybase = (size_t)tt * 2048;
        int colh = (wn >> 1) + t;
        #pragma unroll
        for (int nt = 0; nt < 4; nt++) {
            float o0 = fmaxf(c[nt][0] + bb[nt].x, 0.f);
            float o1 = fmaxf(c[nt][1] + bb[nt].y, 0.f);
            float o2 = fmaxf(c[nt][2] + bb[nt].x, 0.f);
            float o3 = fmaxf(c[nt][3] + bb[nt].y, 0.f);
            Y[ybase + (size_t)(wm + g) * 32 + colh + nt * 4]     = __floats2half2_rn(o0, o1);
            Y[ybase + (size_t)(wm + g + 8) * 32 + colh + nt * 4] = __floats2half2_rn(o2, o3);
        }
    }
}

// ---- fused decoder GEMM: fp16 X -> A (fp16, W rows 0..63), B (fp32, 64..127) -
__global__ void __launch_bounds__(256)
k_gemm_mma_dec(const __half2* __restrict__ X, const float* __restrict__ W,
               __half2* __restrict__ YA, float* __restrict__ YB, int ntiles) {
    __shared__ __half Xs[64][72];
    __shared__ __half WtA[64][72];
    __shared__ __half WtB[64][72];
    int tid = threadIdx.x;
    int warp = tid >> 5, lane = tid & 31;
    int g = lane >> 2, t = lane & 3;
    int wm = (warp >> 1) * 16;
    int wn = (warp & 1) * 32;
    for (int idx = tid; idx < 4096; idx += 256) {
        int k = idx >> 6, n = idx & 63;
        WtA[n][k] = __float2half(W[idx]);
        WtB[n][k] = __float2half(W[idx + 4096]);
    }

    for (int tt = blockIdx.x; tt < ntiles; tt += gridDim.x) {
        __syncthreads();
        size_t hbase = (size_t)tt * 2048;
        const uint4* X4 = (const uint4*)(X + hbase);
        #pragma unroll
        for (int i = 0; i < 2; i++) {
            int idx = tid + i * 256;
            uint4 v = X4[idx];
            int row = idx >> 3;
            int c0  = (idx & 7) * 8;
            *(uint4*)&Xs[row][c0] = v;
        }
        __syncthreads();
        float cA[4][4], cB[4][4];
        #pragma unroll
        for (int nt = 0; nt < 4; nt++) {
            cA[nt][0] = cA[nt][1] = cA[nt][2] = cA[nt][3] = 0.f;
            cB[nt][0] = cB[nt][1] = cB[nt][2] = cB[nt][3] = 0.f;
        }
        #pragma unroll
        for (int kk = 0; kk < 64; kk += 16) {
            unsigned a0 = *(const unsigned*)&Xs[wm + g][kk + 2 * t];
            unsigned a1 = *(const unsigned*)&Xs[wm + g + 8][kk + 2 * t];
            unsigned a2 = *(const unsigned*)&Xs[wm + g][kk + 2 * t + 8];
            unsigned a3 = *(const unsigned*)&Xs[wm + g + 8][kk + 2 * t + 8];
            #pragma unroll
            for (int nt = 0; nt < 4; nt++) {
                int n = wn + nt * 8 + g;
                unsigned b0 = *(const unsigned*)&WtA[n][kk + 2 * t];
                unsigned b1 = *(const unsigned*)&WtA[n][kk + 2 * t + 8];
                mma16816(cA[nt], a0, a1, a2, a3, b0, b1);
                unsigned d0 = *(const unsigned*)&WtB[n][kk + 2 * t];
                unsigned d1 = *(const unsigned*)&WtB[n][kk + 2 * t + 8];
                mma16816(cB[nt], a0, a1, a2, a3, d0, d1);
            }
        }
        size_t yab = (size_t)tt * 2048;
        int colh = (wn >> 1) + t;
        #pragma unroll
        for (int nt = 0; nt < 4; nt++) {
            YA[yab + (size_t)(wm + g) * 32 + colh + nt * 4]     = __floats2half2_rn(cA[nt][0], cA[nt][1]);
            YA[yab + (size_t)(wm + g + 8) * 32 + colh + nt * 4] = __floats2half2_rn(cA[nt][2], cA[nt][3]);
        }
        size_t base = (size_t)tt * 4096;
        #pragma unroll
        for (int nt = 0; nt < 4; nt++) {
            int col = wn + nt * 8 + 2 * t;
            *(float2*)(YB + base + (size_t)(wm + g) * 64 + col)     = make_float2(cB[nt][0], cB[nt][1]);
            *(float2*)(YB + base + (size_t)(wm + g + 8) * 64 + col) = make_float2(cB[nt][2], cB[nt][3]);
        }
    }
}

// ---- decoder, CSR order, fp16 A gather --------------------------------------
__global__ void __launch_bounds__(256)
k_dec_csr(const __half2* __restrict__ A, const float* __restrict__ B,
          const float* __restrict__ b1, const float* __restrict__ w2,
          const float* __restrict__ b2, float* __restrict__ out, int N) {
    int warp = threadIdx.x >> 5, lane = threadIdx.x & 31;
    int n = blockIdx.x * 8 + warp;
    if (n >= N) return;
    int lane2 = lane * 2;
    float2 bias = *(const float2*)(b1 + lane2);
    float2 w    = *(const float2*)(w2 + lane2);
    float  bout = b2[0];
    float2 bc   = *(const float2*)(B + ((size_t)n << 6) + lane2);
    bc.x += bias.x; bc.y += bias.y;
    int st = g_offs[n];
    int en = st + g_cnti[n];
    int k = st;
    #pragma unroll 1
    for (; k + 2 <= en; k += 2) {
        uint2 rec0 = g_csr[k];
        uint2 rec1 = g_csr[k + 1];
        int r0 = (int)rec0.x, r1 = (int)rec1.x;
        float2 a0 = __half22float2(A[((size_t)r0 << 5) + lane]);
        float2 a1 = __half22float2(A[((size_t)r1 << 5) + lane]);
        float s0 = fmaxf(a0.x + bc.x, 0.f) * w.x + fmaxf(a0.y + bc.y, 0.f) * w.y;
        float s1 = fmaxf(a1.x + bc.x, 0.f) * w.x + fmaxf(a1.y + bc.y, 0.f) * w.y;
        #pragma unroll
        for (int off = 16; off; off >>= 1) {
            s0 += __shfl_down_sync(0xffffffffu, s0, off);
            s1 += __shfl_down_sync(0xffffffffu, s1, off);
        }
        if (lane == 0) {
            float v0 = s0 + bout;
            float v1 = s1 + bout;
            if (r0 == n) v0 = fmaxf(v0, 0.f) + log1pf(expf(-fabsf(v0)));
            if (r1 == n) v1 = fmaxf(v1, 0.f) + log1pf(expf(-fabsf(v1)));
            out[g_eid[k]]     = v0;
            out[g_eid[k + 1]] = v1;
        }
    }
    if (k < en) {
        uint2 rec = g_csr[k];
        int r = (int)rec.x;
        float2 a = __half22float2(A[((size_t)r << 5) + lane]);
        float s = fmaxf(a.x + bc.x, 0.f) * w.x + fmaxf(a.y + bc.y, 0.f) * w.y;
        #pragma unroll
        for (int off = 16; off; off >>= 1)
            s += __shfl_down_sync(0xffffffffu, s, off);
        if (lane == 0) {
            float val = s + bout;
            if (r == n) val = fmaxf(val, 0.f) + log1pf(expf(-fabsf(val)));
            out[g_eid[k]] = val;
        }
    }
}

extern "C" void kernel_launch(void* const* d_in, const int* in_sizes, int n_in,
                              void* d_out, int out_size) {
    const float* x        = (const float*)d_in[0];
    const float* eattr    = (const float*)d_in[1];
    const float* w_enc    = (const float*)d_in[2];
    const float* b_enc    = (const float*)d_in[3];
    const float* conv1_w  = (const float*)d_in[4];
    const float* conv1_b  = (const float*)d_in[5];
    const float* conv2_w  = (const float*)d_in[6];
    const float* conv2_b  = (const float*)d_in[7];
    const float* dec_w1   = (const float*)d_in[8];
    const float* dec_b1   = (const float*)d_in[9];
    const float* dec_w2   = (const float*)d_in[10];
    const float* dec_b2   = (const float*)d_in[11];
    const void*  rowp     = d_in[12];
    const void*  colp     = d_in[13];
    float* out = (float*)d_out;

    const int N = in_sizes[0];
    const int E = in_sizes[1];

    float *p_deg, *p_t1;
    int *p_cnti;
    __half2 *p_hh0, *p_hh1, *p_hhT;
    cudaGetSymbolAddress((void**)&p_deg, g_deg);
    cudaGetSymbolAddress((void**)&p_t1,  g_t1);
    cudaGetSymbolAddress((void**)&p_cnti, g_cnti);
    cudaGetSymbolAddress((void**)&p_hh0, g_hh0);
    cudaGetSymbolAddress((void**)&p_hh1, g_hh1);
    cudaGetSymbolAddress((void**)&p_hhT, g_hhT);

    const int TB = 256;
    int eb  = (E + TB - 1) / TB;
    int nb  = (N + TB - 1) / TB;
    int nhb = (N * 32 + TB - 1) / TB;
    int ntiles = (N + 63) / 64;
    int gg  = (ntiles + 1) / 2;
    int ab  = (N + 7) / 8;
    int nsb = (N + 1023) / 1024;

    k_zero2<<<nb, TB>>>(p_deg, p_cnti, N, (const unsigned int*)rowp);
    k_deg_cnt<<<eb, TB>>>(eattr, colp, E);

    k_scan1<<<nsb, 256>>>(N);
    k_scan2<<<1, 128>>>(nsb);
    k_scan3<<<nb, TB>>>(N);
    k_csr_fill<<<eb, TB>>>(eattr, rowp, colp, E);

    // layer 1 (collapsed rank-2 form) -> hh0 (fp16)
    k_uv<<<1, 64>>>(w_enc, b_enc, conv1_w);
    k_l1sums<<<ab, TB>>>(x, N);
    k_l1out<<<nhb, TB>>>(conv1_b, p_hh0, N);

    // layers 2..6: agg(fp16 -> fp16 hhT), MMA gemm h2h (hhT -> nxt)
    const float* Ws[5] = { conv2_w,            conv1_w + 4096, conv2_w + 4096,
                           conv1_w + 2*4096,   conv2_w + 2*4096 };
    const float* Bs[5] = { conv2_b,            conv1_b + 64,   conv2_b + 64,
                           conv1_b + 2*64,     conv2_b + 2*64 };
    __half2* cur = p_hh0;
    __half2* nxt = p_hh1;
    for (int i = 0; i < 5; i++) {
        k_agg<<<ab, TB>>>(cur, p_hhT, N);
        k_gemm_mma_h2h<<<gg, TB>>>(p_hhT, Ws[i], Bs[i], nxt, ntiles);
        { __half2* t = cur; cur = nxt; nxt = t; }
    }
    // after 5 layers: cur = hh1, nxt = hh0 (free)

    // fused decoder GEMM: A (fp16) -> nxt, B (fp32) -> t1
    k_gemm_mma_dec<<<gg, TB>>>(cur, dec_w1, nxt, p_t1, ntiles);
    k_dec_csr<<<ab, TB>>>(nxt, p_t1, dec_b1, dec_w2, dec_b2, out, N);
}